// round 1
// baseline (speedup 1.0000x reference)
#include <cuda_runtime.h>
#include <math.h>

#define B_   2
#define LQ_  1024
#define LK_  1024
#define D_   1024
#define H_   16
#define DH_  64
#define BH_  (B_ * H_)
#define NEG_BIG (-3.402823466e38f)

// ---------------- scratch (static device globals: allocation-guard safe) ----
__device__ float g_q[B_ * LQ_ * D_];            // 8 MB   projected Q
__device__ float g_k[B_ * LK_ * D_];            // 8 MB   projected K
__device__ float g_v[B_ * LK_ * D_];            // 8 MB   projected V
__device__ float g_s[(size_t)BH_ * LQ_ * LK_];  // 134 MB scores / probs
__device__ float g_att[B_ * LQ_ * D_];          // 8 MB   attn output (concat heads)
__device__ int   g_mask_kind;                   // 0=int32, 1=float32, 2=byte

// ---------------- mask dtype detection -------------------------------------
// Reads the first 2048 bytes (safe whether the mask buffer is 2048 int32,
// 2048 float32, or 2048 uint8 elements) and classifies the representation.
__global__ void detect_mask_kernel(const unsigned int* m) {
    if (threadIdx.x == 0 && blockIdx.x == 0) {
        int all01 = 1, allf = 1;
        for (int i = 0; i < 512; i++) {
            unsigned v = m[i];
            if (v > 1u) all01 = 0;
            if (v != 0u && v != 0x3F800000u) allf = 0;
        }
        g_mask_kind = all01 ? 0 : (allf ? 1 : 2);
    }
}

__device__ __forceinline__ bool mask_true(const void* m, int kind, int idx) {
    if (kind == 0) return ((const int*)m)[idx] != 0;
    if (kind == 1) return ((const float*)m)[idx] != 0.0f;
    return ((const unsigned char*)m)[idx] != 0;
}

// ---------------- GEMM: C[M,1024] = A[M,1024] @ W[1024,1024]^T + bias ------
// 64x64 tile, BK=16, 256 threads, 4x4 micro-tile.
__global__ __launch_bounds__(256) void gemm_nt_kernel(
    const float* __restrict__ A, const float* __restrict__ W,
    const float* __restrict__ bias, float* __restrict__ C)
{
    __shared__ float As[64][17];
    __shared__ float Ws[64][17];

    const int tid = threadIdx.x;
    const int tx = tid & 15, ty = tid >> 4;
    const int m0 = blockIdx.y * 64, n0 = blockIdx.x * 64;
    const int lr = tid >> 2;            // 0..63
    const int lc = (tid & 3) * 4;       // 0,4,8,12

    float acc[4][4] = {};

    for (int kt = 0; kt < 1024; kt += 16) {
        float4 av = *(const float4*)&A[(size_t)(m0 + lr) * 1024 + kt + lc];
        As[lr][lc] = av.x; As[lr][lc+1] = av.y; As[lr][lc+2] = av.z; As[lr][lc+3] = av.w;
        float4 wv = *(const float4*)&W[(size_t)(n0 + lr) * 1024 + kt + lc];
        Ws[lr][lc] = wv.x; Ws[lr][lc+1] = wv.y; Ws[lr][lc+2] = wv.z; Ws[lr][lc+3] = wv.w;
        __syncthreads();

        #pragma unroll
        for (int kk = 0; kk < 16; kk++) {
            float a[4], b[4];
            #pragma unroll
            for (int i = 0; i < 4; i++) a[i] = As[ty * 4 + i][kk];
            #pragma unroll
            for (int j = 0; j < 4; j++) b[j] = Ws[tx * 4 + j][kk];
            #pragma unroll
            for (int i = 0; i < 4; i++)
                #pragma unroll
                for (int j = 0; j < 4; j++)
                    acc[i][j] += a[i] * b[j];
        }
        __syncthreads();
    }

    #pragma unroll
    for (int i = 0; i < 4; i++) {
        int m = m0 + ty * 4 + i;
        #pragma unroll
        for (int j = 0; j < 4; j++) {
            int n = n0 + tx * 4 + j;
            C[(size_t)m * 1024 + n] = acc[i][j] + bias[n];
        }
    }
}

// ---------------- scores: S[b,h,q,k] = scale*Qh.Kh^T + mask/bias ------------
// grid (LK/64, LQ/64, B*H); one 64x64 tile per block, full K=64 in smem.
__global__ __launch_bounds__(256) void scores_kernel(
    const void* __restrict__ mask, const float* __restrict__ lb)
{
    const int bh = blockIdx.z;
    const int b = bh >> 4, h = bh & 15;
    const int hc = h * DH_;
    const int q0 = blockIdx.y * 64, k0 = blockIdx.x * 64;

    __shared__ float Qs[64][65];
    __shared__ float Ks[64][65];

    const int tid = threadIdx.x;
    const int tx = tid & 15, ty = tid >> 4;
    const int lr = tid >> 4;            // 0..15
    const int lc = (tid & 15) * 4;      // 0..60

    #pragma unroll
    for (int w = 0; w < 64; w += 16) {
        float4 qv = *(const float4*)&g_q[(size_t)(b * LQ_ + q0 + lr + w) * D_ + hc + lc];
        Qs[lr + w][lc] = qv.x; Qs[lr + w][lc+1] = qv.y; Qs[lr + w][lc+2] = qv.z; Qs[lr + w][lc+3] = qv.w;
        float4 kv = *(const float4*)&g_k[(size_t)(b * LK_ + k0 + lr + w) * D_ + hc + lc];
        Ks[lr + w][lc] = kv.x; Ks[lr + w][lc+1] = kv.y; Ks[lr + w][lc+2] = kv.z; Ks[lr + w][lc+3] = kv.w;
    }
    __syncthreads();

    float acc[4][4] = {};
    #pragma unroll
    for (int kk = 0; kk < 64; kk++) {
        float a[4], bb[4];
        #pragma unroll
        for (int i = 0; i < 4; i++) a[i] = Qs[ty * 4 + i][kk];
        #pragma unroll
        for (int j = 0; j < 4; j++) bb[j] = Ks[tx * 4 + j][kk];
        #pragma unroll
        for (int i = 0; i < 4; i++)
            #pragma unroll
            for (int j = 0; j < 4; j++)
                acc[i][j] += a[i] * bb[j];
    }

    const float scale = 0.125f;   // 1/sqrt(64)
    const int kind = g_mask_kind;

    #pragma unroll
    for (int i = 0; i < 4; i++) {
        int q = q0 + ty * 4 + i;
        #pragma unroll
        for (int j = 0; j < 4; j++) {
            int k = k0 + tx * 4 + j;
            bool mk = mask_true(mask, kind, b * LK_ + k);
            float add = mk ? NEG_BIG : lb[(size_t)(b * LQ_ + q) * LK_ + k];
            g_s[((size_t)bh * LQ_ + q) * LK_ + k] = acc[i][j] * scale + add;
        }
    }
}

// ---------------- row softmax over LK=1024, one block per row ---------------
__global__ __launch_bounds__(256) void softmax_kernel() {
    const size_t row = blockIdx.x;
    float* s = &g_s[row * LK_];
    const int tid = threadIdx.x;
    const int lane = tid & 31, wid = tid >> 5;

    float4 v = *(float4*)&s[tid * 4];
    float m = fmaxf(fmaxf(v.x, v.y), fmaxf(v.z, v.w));
    #pragma unroll
    for (int o = 16; o > 0; o >>= 1) m = fmaxf(m, __shfl_xor_sync(0xffffffffu, m, o));

    __shared__ float red[8];
    if (lane == 0) red[wid] = m;
    __syncthreads();
    float bm = red[0];
    #pragma unroll
    for (int i = 1; i < 8; i++) bm = fmaxf(bm, red[i]);

    float e0 = __expf(v.x - bm), e1 = __expf(v.y - bm);
    float e2 = __expf(v.z - bm), e3 = __expf(v.w - bm);
    float sum = e0 + e1 + e2 + e3;
    #pragma unroll
    for (int o = 16; o > 0; o >>= 1) sum += __shfl_xor_sync(0xffffffffu, sum, o);

    __shared__ float red2[8];
    if (lane == 0) red2[wid] = sum;
    __syncthreads();
    float tot = 0.0f;
    #pragma unroll
    for (int i = 0; i < 8; i++) tot += red2[i];

    float inv = 1.0f / tot;
    float4 o4 = make_float4(e0 * inv, e1 * inv, e2 * inv, e3 * inv);
    *(float4*)&s[tid * 4] = o4;
}

// ---------------- PV: att[b,q,hc+d] = sum_k P[bh,q,k] * Vh[b,k,hc+d] --------
// grid (LQ/64, B*H). M=1024 per bh, N=64, K=1024.
__global__ __launch_bounds__(256) void pv_kernel() {
    const int bh = blockIdx.y;
    const int b = bh >> 4, h = bh & 15;
    const int hc = h * DH_;
    const int m0 = blockIdx.x * 64;

    __shared__ float Ps[64][17];
    __shared__ float Vs[16][65];

    const int tid = threadIdx.x;
    const int tx = tid & 15, ty = tid >> 4;
    const int pr = tid >> 2, pc = (tid & 3) * 4;     // P loader: 64x16
    const int vr = tid >> 4, vc = (tid & 15) * 4;    // V loader: 16x64

    float acc[4][4] = {};

    for (int kt = 0; kt < 1024; kt += 16) {
        float4 pv = *(const float4*)&g_s[((size_t)bh * LQ_ + m0 + pr) * LK_ + kt + pc];
        Ps[pr][pc] = pv.x; Ps[pr][pc+1] = pv.y; Ps[pr][pc+2] = pv.z; Ps[pr][pc+3] = pv.w;
        float4 vv = *(const float4*)&g_v[(size_t)(b * LK_ + kt + vr) * D_ + hc + vc];
        Vs[vr][vc] = vv.x; Vs[vr][vc+1] = vv.y; Vs[vr][vc+2] = vv.z; Vs[vr][vc+3] = vv.w;
        __syncthreads();

        #pragma unroll
        for (int kk = 0; kk < 16; kk++) {
            float a[4], bb[4];
            #pragma unroll
            for (int i = 0; i < 4; i++) a[i] = Ps[ty * 4 + i][kk];
            #pragma unroll
            for (int j = 0; j < 4; j++) bb[j] = Vs[kk][tx * 4 + j];
            #pragma unroll
            for (int i = 0; i < 4; i++)
                #pragma unroll
                for (int j = 0; j < 4; j++)
                    acc[i][j] += a[i] * bb[j];
        }
        __syncthreads();
    }

    #pragma unroll
    for (int i = 0; i < 4; i++) {
        int q = m0 + ty * 4 + i;
        #pragma unroll
        for (int j = 0; j < 4; j++)
            g_att[(size_t)(b * LQ_ + q) * D_ + hc + tx * 4 + j] = acc[i][j];
    }
}

// ---------------- launch ----------------------------------------------------
extern "C" void kernel_launch(void* const* d_in, const int* in_sizes, int n_in,
                              void* d_out, int out_size)
{
    const float* q    = (const float*)d_in[0];
    const float* k    = (const float*)d_in[1];
    const float* v    = (const float*)d_in[2];
    const float* Wq   = (const float*)d_in[3];
    const float* bq   = (const float*)d_in[4];
    const float* Wk   = (const float*)d_in[5];
    const float* bk   = (const float*)d_in[6];
    const float* Wv   = (const float*)d_in[7];
    const float* bv   = (const float*)d_in[8];
    const float* Wo   = (const float*)d_in[9];
    const float* bo   = (const float*)d_in[10];
    const float* lb   = (const float*)d_in[11];
    const void*  mask = (const void*)d_in[12];
    float* out = (float*)d_out;

    float *pq, *pk, *pv, *patt;
    cudaGetSymbolAddress((void**)&pq,   g_q);
    cudaGetSymbolAddress((void**)&pk,   g_k);
    cudaGetSymbolAddress((void**)&pv,   g_v);
    cudaGetSymbolAddress((void**)&patt, g_att);

    detect_mask_kernel<<<1, 32>>>((const unsigned int*)mask);

    dim3 gproj(16, 32);                   // N/64 x (B*LQ)/64
    gemm_nt_kernel<<<gproj, 256>>>(q, Wq, bq, pq);
    gemm_nt_kernel<<<gproj, 256>>>(k, Wk, bk, pk);
    gemm_nt_kernel<<<gproj, 256>>>(v, Wv, bv, pv);

    dim3 gsc(LK_ / 64, LQ_ / 64, BH_);
    scores_kernel<<<gsc, 256>>>(mask, lb);

    softmax_kernel<<<BH_ * LQ_, 256>>>();

    dim3 gpv(LQ_ / 64, BH_);
    pv_kernel<<<gpv, 256>>>();

    gemm_nt_kernel<<<gproj, 256>>>(patt, Wo, bo, out);
}